// round 14
// baseline (speedup 1.0000x reference)
#include <cuda_runtime.h>
#include <cuda_bf16.h>
#include <cstdint>

// ---------------------------------------------------------------------------
// VectorQuantizer -- mma.sync (HMMA bf16) bf16x3 candidate GEMM + exact refine
//   z   : [32, 256, 32, 32] fp32   (B, D, H, W)
//   emb : [1024, 256] fp32         (K, D)
// outputs (concatenated fp32 in d_out):
//   [0] loss | [1..) z_q [B,D,H,W] | [8388609] perplexity |
//   [8388610..) one-hot [N,K] | [41943042..) idx [B,H,W] as float
//
// tcgen05 is unavailable (harness targets compute_103 without the 'a' feature
// set), so the approximate distance GEMM uses baseline sm_80+ PTX:
// mma.sync.m16n8k16.bf16 with fp32 accum, 3 passes (zhi*ehi + zhi*elo +
// zlo*ehi; dropped lo*lo term ~2e-7 << DELTA). Each thread collects
// candidates with v <= thread_running_min + DELTA over its disjoint 1/4 of
// codes per token row (provable superset of the exact-argmin tie set, slack
// ~7e-5 << 1e-3), then refine re-evaluates candidates with the bit-exact
// sequential FFMA chain + RN(RN(zz+ee)-2*acc) + min-index tie-break (proven
// in R4 to match the reference exactly).
// ---------------------------------------------------------------------------

#define Dd     256
#define Kk     1024
#define NTOK   32768
#define NELEM  8388608

#define OFF_LOSS 0
#define OFF_ZQ   1
#define OFF_PERP 8388609
#define OFF_ME   8388610
#define OFF_IDX  41943042

#define DELTA    1e-3f
#define AST      40            // smem row stride in bf16 (80B; conflict-free)

// ---- scratch (static device globals -- no allocation allowed) -------------
__device__ float g_enorm[Kk];
__device__ float g_znorm[NTOK];
__device__ int   g_idx[NTOK];
__device__ int   g_count[Kk];
__device__ float g_partial[8192];
__device__ __align__(16) float         g_zf [NTOK * Dd];
__device__ __align__(16) __nv_bfloat16 g_zhi[NTOK * Dd];
__device__ __align__(16) __nv_bfloat16 g_zlo[NTOK * Dd];
__device__ __align__(16) __nv_bfloat16 g_ehi[Kk * Dd];
__device__ __align__(16) __nv_bfloat16 g_elo[Kk * Dd];
__device__ int           g_cand[NTOK * 16];     // 4 quarters x 4 slots
__device__ unsigned char g_ccnt4[NTOK * 4];     // per-quarter count, 255=ovf

// ---------------------------------------------------------------------------
__device__ __forceinline__ uint32_t smem_u32(const void* p) {
    uint32_t a;
    asm("{ .reg .u64 t; cvta.to.shared.u64 t, %1; cvt.u32.u64 %0, t; }"
        : "=r"(a) : "l"(p));
    return a;
}

#define LDSM_X4(r0, r1, r2, r3, addr) \
    asm volatile("ldmatrix.sync.aligned.m8n8.x4.shared.b16 {%0,%1,%2,%3}, [%4];" \
                 : "=r"(r0), "=r"(r1), "=r"(r2), "=r"(r3) : "r"(addr))

#define MMA_BF16(d, a, b0, b1) \
    asm volatile("mma.sync.aligned.m16n8k16.row.col.f32.bf16.bf16.f32 " \
                 "{%0,%1,%2,%3}, {%4,%5,%6,%7}, {%8,%9}, {%0,%1,%2,%3};" \
                 : "+f"((d)[0]), "+f"((d)[1]), "+f"((d)[2]), "+f"((d)[3]) \
                 : "r"((a)[0]), "r"((a)[1]), "r"((a)[2]), "r"((a)[3]), \
                   "r"(b0), "r"(b1))

// ---------------------------------------------------------------------------
__global__ void reset_kernel() {
    int t = threadIdx.x;
    if (t < Kk) g_count[t] = 0;
}

// ---------------------------------------------------------------------------
// prep_e: ||e_k||^2 + bf16 hi/lo split (row-major [K][256])
// ---------------------------------------------------------------------------
__global__ void prep_e_kernel(const float* __restrict__ emb) {
    int k    = blockIdx.x;
    int lane = threadIdx.x;
    const float4* row = (const float4*)(emb + (size_t)k * Dd);
    float4 a = row[lane];
    float4 b = row[32 + lane];
    float va[8] = {a.x, a.y, a.z, a.w, b.x, b.y, b.z, b.w};
    int   di[8] = {lane*4, lane*4+1, lane*4+2, lane*4+3,
                   128+lane*4, 128+lane*4+1, 128+lane*4+2, 128+lane*4+3};
    float s = 0.0f;
    #pragma unroll
    for (int j = 0; j < 8; ++j) {
        float x = va[j];
        s += x * x;
        __nv_bfloat16 h = __float2bfloat16(x);
        float hf = __bfloat162float(h);
        __nv_bfloat16 l = __float2bfloat16(x - hf);
        g_ehi[(size_t)k * Dd + di[j]] = h;
        g_elo[(size_t)k * Dd + di[j]] = l;
    }
    #pragma unroll
    for (int o = 16; o > 0; o >>= 1)
        s += __shfl_xor_sync(0xFFFFFFFFu, s, o);
    if (lane == 0) g_enorm[k] = s;
}

// ---------------------------------------------------------------------------
// prep_z: transpose z -> zf rows + bf16 hi/lo split + XLA-order ||z||^2
// ---------------------------------------------------------------------------
__global__ __launch_bounds__(256)
void prep_z_kernel(const float* __restrict__ z) {
    __shared__ float zs[256 * 33];
    const int n0 = blockIdx.x * 32;
    const int b  = n0 >> 10;
    const int r0 = n0 & 1023;
    const float* zb = z + (size_t)b * (Dd * 1024) + r0;

    const int tid = threadIdx.x;
    const int lr  = tid & 31;
    const int dg  = tid >> 5;
    #pragma unroll
    for (int dd = 0; dd < 256; dd += 8)
        zs[(dd + dg) * 33 + lr] = __ldg(zb + (size_t)(dd + dg) * 1024 + lr);
    __syncthreads();

    #pragma unroll 4
    for (int tok = 0; tok < 32; ++tok) {
        float x = zs[tid * 33 + tok];
        size_t o = (size_t)(n0 + tok) * Dd + tid;
        g_zf[o] = x;
        __nv_bfloat16 h = __float2bfloat16(x);
        float hf = __bfloat162float(h);
        g_zhi[o] = h;
        g_zlo[o] = __float2bfloat16(x - hf);
    }

    const int w = tid >> 5;
    const int t = tid & 31;
    #pragma unroll
    for (int q = 0; q < 4; ++q) {
        const int tok = w * 4 + q;
        float acc = 0.0f;
        #pragma unroll
        for (int i = 0; i < 8; ++i) {
            float x = zs[(t + 32 * i) * 33 + tok];
            acc = __fadd_rn(acc, __fmul_rn(x, x));
        }
        #pragma unroll
        for (int o = 16; o > 0; o >>= 1)
            acc = __fadd_rn(acc, __shfl_down_sync(0xFFFFFFFFu, acc, o));
        if (t == 0) g_znorm[n0 + tok] = acc;
    }
}

// ---------------------------------------------------------------------------
// gemm_cand: block = 256 thr (8 warps), 128 tokens x 1024 codes.
// Warp w owns token rows w*16..w*16+15. Chunks: 128 codes x 32 dims.
// Accumulate 3 bf16 mma passes into fp32; per-thread candidate lists.
// ---------------------------------------------------------------------------
__global__ __launch_bounds__(256)
void gemm_cand_kernel() {
    __shared__ __nv_bfloat16 sAh[128 * AST];
    __shared__ __nv_bfloat16 sAl[128 * AST];
    __shared__ __nv_bfloat16 sBh[128 * AST];
    __shared__ __nv_bfloat16 sBl[128 * AST];

    const int tid  = threadIdx.x;
    const int warp = tid >> 5;
    const int lane = tid & 31;
    const int g    = lane >> 2;
    const int t    = lane & 3;
    const int n0   = blockIdx.x * 128;
    const int mbase = warp * 16;

    const uint32_t aAh = smem_u32(sAh), aAl = smem_u32(sAl);
    const uint32_t aBh = smem_u32(sBh), aBl = smem_u32(sBl);

    // ldmatrix lane->address components
    const int lm  = lane >> 3;         // matrix id 0..3
    const int lr  = lane & 7;          // row within matrix
    // A: row = mbase + lr + (lm&1)*8 ; col = kof + (lm>>1)*8
    const int arow = mbase + lr + (lm & 1) * 8;
    // B: row = nbase + lr + (lm>>1)*8 ; col = kof + (lm&1)*8
    const int brow_off = lr + (lm >> 1) * 8;
    const int bk_off   = (lm & 1) * 8;
    const int ak_off   = (lm >> 1) * 8;

    // gmem->smem staging: thread loads 16 bf16 (2 x uint4) per array
    const int ldr = tid >> 1;          // row 0..127
    const int ldp = tid & 1;           // 16-elem half of 32-dim chunk

    // per-thread candidate state: 2 token rows (g, g+8)
    float cmin[2] = {3.4e38f, 3.4e38f};
    float cval[2][4];
    int   ckey[2][4];
    int   ccnt[2] = {0, 0};
    int   covf = 0;

    for (int nc = 0; nc < 8; ++nc) {           // 128 codes per chunk
        float acc[16][4];
        #pragma unroll
        for (int i = 0; i < 16; ++i)
            #pragma unroll
            for (int j = 0; j < 4; ++j) acc[i][j] = 0.0f;

        for (int kc = 0; kc < 8; ++kc) {       // 32 dims per chunk
            __syncthreads();
            {
                size_t za = (size_t)(n0 + ldr) * Dd + kc * 32 + ldp * 16;
                size_t ea = (size_t)(nc * 128 + ldr) * Dd + kc * 32 + ldp * 16;
                const uint4* p;
                uint4 v0, v1;
                p = (const uint4*)(g_zhi + za); v0 = __ldg(p); v1 = __ldg(p + 1);
                *(uint4*)(sAh + ldr * AST + ldp * 16)     = v0;
                *(uint4*)(sAh + ldr * AST + ldp * 16 + 8) = v1;
                p = (const uint4*)(g_zlo + za); v0 = __ldg(p); v1 = __ldg(p + 1);
                *(uint4*)(sAl + ldr * AST + ldp * 16)     = v0;
                *(uint4*)(sAl + ldr * AST + ldp * 16 + 8) = v1;
                p = (const uint4*)(g_ehi + ea); v0 = __ldg(p); v1 = __ldg(p + 1);
                *(uint4*)(sBh + ldr * AST + ldp * 16)     = v0;
                *(uint4*)(sBh + ldr * AST + ldp * 16 + 8) = v1;
                p = (const uint4*)(g_elo + ea); v0 = __ldg(p); v1 = __ldg(p + 1);
                *(uint4*)(sBl + ldr * AST + ldp * 16)     = v0;
                *(uint4*)(sBl + ldr * AST + ldp * 16 + 8) = v1;
            }
            __syncthreads();

            #pragma unroll
            for (int ks = 0; ks < 2; ++ks) {   // two k16 steps
                const int kof = ks * 16;
                uint32_t ah[4], al[4];
                uint32_t aadr = 2u * (uint32_t)(arow * AST + kof + ak_off);
                LDSM_X4(ah[0], ah[1], ah[2], ah[3], aAh + aadr);
                LDSM_X4(al[0], al[1], al[2], al[3], aAl + aadr);
                #pragma unroll
                for (int np = 0; np < 8; ++np) {   // pairs of n8 tiles
                    uint32_t bh[4], bl[4];
                    uint32_t badr = 2u * (uint32_t)((np * 16 + brow_off) * AST
                                                    + kof + bk_off);
                    LDSM_X4(bh[0], bh[1], bh[2], bh[3], aBh + badr);
                    LDSM_X4(bl[0], bl[1], bl[2], bl[3], aBl + badr);
                    MMA_BF16(acc[np * 2 + 0], ah, bh[0], bh[1]);
                    MMA_BF16(acc[np * 2 + 0], ah, bl[0], bl[1]);
                    MMA_BF16(acc[np * 2 + 0], al, bh[0], bh[1]);
                    MMA_BF16(acc[np * 2 + 1], ah, bh[2], bh[3]);
                    MMA_BF16(acc[np * 2 + 1], ah, bl[2], bl[3]);
                    MMA_BF16(acc[np * 2 + 1], al, bh[2], bh[3]);
                }
            }
        }

        // epilogue: c-frag (i<2 -> row g, i>=2 -> row g+8; col = t*2+(i&1))
        #pragma unroll
        for (int nt = 0; nt < 16; ++nt) {
            #pragma unroll
            for (int i = 0; i < 4; ++i) {
                const int tk = i >> 1;
                float v = -2.0f * acc[nt][i];
                if (v <= cmin[tk] + DELTA) {
                    int code = nc * 128 + nt * 8 + t * 2 + (i & 1);
                    if (ccnt[tk] < 4) {
                        cval[tk][ccnt[tk]] = v;
                        ckey[tk][ccnt[tk]] = code;
                        ++ccnt[tk];
                    } else covf = 1;
                    if (v < cmin[tk]) cmin[tk] = v;
                }
            }
        }
    }

    // write pruned per-quarter candidate lists
    #pragma unroll
    for (int tk = 0; tk < 2; ++tk) {
        const int token = n0 + mbase + g + tk * 8;
        int m = 0;
        for (int i = 0; i < ccnt[tk]; ++i) {
            if (cval[tk][i] <= cmin[tk] + DELTA)
                g_cand[(size_t)token * 16 + t * 4 + (m++)] = ckey[tk][i];
        }
        g_ccnt4[token * 4 + t] = covf ? 255 : (unsigned char)m;
    }
}

// ---------------------------------------------------------------------------
// refine: exact sequential-FFMA-chain distance, bit-exact R4 argmin.
// ---------------------------------------------------------------------------
__device__ __forceinline__ float exact_d(const float* __restrict__ zr,
                                         const float* __restrict__ er,
                                         float zz, float ee) {
    float acc = 0.0f;
    #pragma unroll 8
    for (int d = 0; d < Dd; d += 4) {
        float4 a = *(const float4*)(zr + d);
        float4 b = __ldg((const float4*)(er + d));
        acc = __fmaf_rn(a.x, b.x, acc);
        acc = __fmaf_rn(a.y, b.y, acc);
        acc = __fmaf_rn(a.z, b.z, acc);
        acc = __fmaf_rn(a.w, b.w, acc);
    }
    float t1 = __fadd_rn(zz, ee);
    return __fmaf_rn(-2.0f, acc, t1);
}

__global__ __launch_bounds__(256)
void refine_kernel(const float* __restrict__ emb,
                   float* __restrict__ out_idx) {
    const int w    = threadIdx.x >> 5;
    const int lane = threadIdx.x & 31;
    const int n    = blockIdx.x * 8 + w;

    const float zz  = g_znorm[n];
    const float* zr = g_zf + (size_t)n * Dd;

    int  myk = -1;
    bool ovf = false;
    if (lane < 16) {
        const int q = lane >> 2, s = lane & 3;
        const int c = g_ccnt4[n * 4 + q];
        if (c == 255) ovf = true;
        else if (s < c) myk = g_cand[(size_t)n * 16 + q * 4 + s];
    }
    const unsigned ob = __ballot_sync(0xFFFFFFFFu, ovf);

    float bv = 3.4e38f;
    int   bk = 0x3FFFFFFF;
    if (ob) {                              // overflow: exact full scan
        for (int k = lane; k < Kk; k += 32) {
            float v = exact_d(zr, emb + (size_t)k * Dd, zz, g_enorm[k]);
            if (v < bv || (v == bv && k < bk)) { bv = v; bk = k; }
        }
    } else if (myk >= 0) {
        bv = exact_d(zr, emb + (size_t)myk * Dd, zz, g_enorm[myk]);
        bk = myk;
    }
    #pragma unroll
    for (int o = 16; o > 0; o >>= 1) {
        float ov = __shfl_down_sync(0xFFFFFFFFu, bv, o);
        int   ok = __shfl_down_sync(0xFFFFFFFFu, bk, o);
        if (ov < bv || (ov == bv && ok < bk)) { bv = ov; bk = ok; }
    }
    if (lane == 0) {
        g_idx[n]   = bk;
        out_idx[n] = (float)bk;
        atomicAdd(&g_count[bk], 1);
    }
}

// ---------------------------------------------------------------------------
__global__ void zero_me_kernel(float* __restrict__ me) {
    float2* p = (float2*)me;
    const int g = blockIdx.x * 256 + threadIdx.x;
    #pragma unroll
    for (int i = 0; i < 8; ++i)
        p[g + i * 2097152] = make_float2(0.0f, 0.0f);
}

__global__ void ones_kernel(float* __restrict__ me) {
    const int n = blockIdx.x * 256 + threadIdx.x;
    me[(size_t)n * Kk + g_idx[n]] = 1.0f;
}

// ---------------------------------------------------------------------------
__global__ __launch_bounds__(256)
void zq_loss_kernel(const float* __restrict__ z,
                    const float* __restrict__ emb,
                    float* __restrict__ zq_out)
{
    __shared__ float red[256];
    const int g    = blockIdx.x * 256 + threadIdx.x;
    const int flat = g * 4;
    const int d    = (flat >> 10) & 255;
    const int b    = flat >> 18;
    const int rem  = flat & 1023;
    const int n    = b * 1024 + rem;

    float4 zv = *(const float4*)(z + flat);

    float q0 = emb[(size_t)g_idx[n + 0] * Dd + d];
    float q1 = emb[(size_t)g_idx[n + 1] * Dd + d];
    float q2 = emb[(size_t)g_idx[n + 2] * Dd + d];
    float q3 = emb[(size_t)g_idx[n + 3] * Dd + d];

    zq_out[flat + 0] = q0;
    zq_out[flat + 1] = q1;
    zq_out[flat + 2] = q2;
    zq_out[flat + 3] = q3;

    float d0 = q0 - zv.x, d1 = q1 - zv.y, d2 = q2 - zv.z, d3 = q3 - zv.w;
    float s = d0*d0 + d1*d1 + d2*d2 + d3*d3;

    red[threadIdx.x] = s;
    __syncthreads();
    #pragma unroll
    for (int o = 128; o > 0; o >>= 1) {
        if (threadIdx.x < o) red[threadIdx.x] += red[threadIdx.x + o];
        __syncthreads();
    }
    if (threadIdx.x == 0) g_partial[blockIdx.x] = red[0];
}

// ---------------------------------------------------------------------------
__global__ void finalize_kernel(float* __restrict__ out) {
    __shared__ float sdata[1024];
    const int t = threadIdx.x;

    float s = 0.0f;
    #pragma unroll
    for (int i = 0; i < 8; ++i) s += g_partial[t + i * 1024];
    sdata[t] = s;
    __syncthreads();
    #pragma unroll
    for (int o = 512; o > 0; o >>= 1) {
        if (t < o) sdata[t] += sdata[t + o];
        __syncthreads();
    }
    if (t == 0) out[OFF_LOSS] = 1.25f * sdata[0] / (float)NELEM;
    __syncthreads();

    float em = (float)g_count[t] * (1.0f / (float)NTOK);
    sdata[t] = em * logf(em + 1e-10f);
    __syncthreads();
    #pragma unroll
    for (int o = 512; o > 0; o >>= 1) {
        if (t < o) sdata[t] += sdata[t + o];
        __syncthreads();
    }
    if (t == 0) out[OFF_PERP] = expf(-sdata[0]);
}

// ---------------------------------------------------------------------------
extern "C" void kernel_launch(void* const* d_in, const int* in_sizes, int n_in,
                              void* d_out, int out_size)
{
    const float* z   = (const float*)d_in[0];
    const float* emb = (const float*)d_in[1];
    float*       o   = (float*)d_out;

    reset_kernel<<<1, 1024>>>();
    prep_e_kernel<<<Kk, 32>>>(emb);
    prep_z_kernel<<<NTOK / 32, 256>>>(z);
    zero_me_kernel<<<8192, 256>>>(o + OFF_ME);
    gemm_cand_kernel<<<NTOK / 128, 256>>>();
    refine_kernel<<<NTOK / 8, 256>>>(emb, o + OFF_IDX);
    ones_kernel<<<NTOK / 256, 256>>>(o + OFF_ME);
    zq_loss_kernel<<<NELEM / 1024, 256>>>(z, emb, o + OFF_ZQ);
    finalize_kernel<<<1, 1024>>>(o);
}